// round 4
// baseline (speedup 1.0000x reference)
#include <cuda_runtime.h>
#include <math.h>

// Problem constants (match reference_code)
#define NU      100000
#define NI      50000
#define NN      (NU + NI)          // 150000 nodes
#define EK      64
#define FEATN   1024
#define NE      3000000            // undirected (bipartite) edges
#define BATCHN  16384
#define NKF     (NN * EK)          // 9,600,000 floats per node-embedding buffer

// ---------------- scratch (static device globals; no runtime allocation) ---
__device__ float g_buf0[NKF];
__device__ float g_buf1[NKF];
__device__ float g_acc[NKF];
__device__ int   g_deg[NN];
__device__ float g_dinv[NN];
__device__ float g_proj[BATCHN * EK];

// ---------------- degree / norm ----------------
__global__ void k_zero_deg() {
    int i = blockIdx.x * blockDim.x + threadIdx.x;
    if (i < NN) g_deg[i] = 0;
}

__global__ void k_count(const int* __restrict__ ue, const int* __restrict__ ie) {
    int e = blockIdx.x * blockDim.x + threadIdx.x;
    if (e < NE) {
        atomicAdd(&g_deg[ue[e]], 1);
        atomicAdd(&g_deg[NU + ie[e]], 1);
    }
}

__global__ void k_dinv() {
    int i = blockIdx.x * blockDim.x + threadIdx.x;
    if (i < NN) {
        int d = g_deg[i];
        g_dinv[i] = (d > 0) ? rsqrtf((float)d) : 0.0f;
    }
}

// ---------------- init: x0 = concat(Gu, Gi); acc = x0 ----------------
__global__ void k_init(const float* __restrict__ Gu, const float* __restrict__ Gi) {
    int i = blockIdx.x * blockDim.x + threadIdx.x;   // float4 index
    const int n4 = NKF / 4;
    if (i < n4) {
        const int gu4 = (NU * EK) / 4;
        float4 v = (i < gu4) ? ((const float4*)Gu)[i]
                             : ((const float4*)Gi)[i - gu4];
        ((float4*)g_buf0)[i] = v;
        ((float4*)g_acc)[i]  = v;
    }
}

// ---------------- per-layer ----------------
__global__ void k_zeroY(int flip) {
    float* Y = flip ? g_buf0 : g_buf1;
    int i = blockIdx.x * blockDim.x + threadIdx.x;
    if (i < NKF / 4) ((float4*)Y)[i] = make_float4(0.f, 0.f, 0.f, 0.f);
}

// warp per undirected edge: lanes 0-15 do u->item, lanes 16-31 do item->u.
// Each lane moves one float4 (16 lanes * 4 = 64 floats per direction).
__global__ void k_scatter(const int* __restrict__ ue, const int* __restrict__ ie, int flip) {
    const float* __restrict__ X = flip ? g_buf1 : g_buf0;
    float* __restrict__ Y       = flip ? g_buf0 : g_buf1;
    int w = (blockIdx.x * blockDim.x + threadIdx.x) >> 5;
    if (w >= NE) return;
    int lane = threadIdx.x & 31;

    int u  = ue[w];
    int it = NU + ie[w];
    float norm = g_dinv[u] * g_dinv[it];

    int half = lane >> 4;
    int l    = lane & 15;
    int src  = half ? it : u;
    int dst  = half ? u  : it;

    float4 v = *(const float4*)(X + (size_t)src * EK + l * 4);
    float* p = Y + (size_t)dst * EK + l * 4;
    asm volatile("red.global.add.v4.f32 [%0], {%1, %2, %3, %4};"
                 :: "l"(p), "f"(v.x * norm), "f"(v.y * norm),
                    "f"(v.z * norm), "f"(v.w * norm)
                 : "memory");
}

__global__ void k_accadd(int flip) {
    const float* __restrict__ Y = flip ? g_buf0 : g_buf1;
    int i = blockIdx.x * blockDim.x + threadIdx.x;
    if (i < NKF / 4) {
        float4 a = ((float4*)g_acc)[i];
        float4 y = ((const float4*)Y)[i];
        a.x += y.x; a.y += y.y; a.z += y.z; a.w += y.w;
        ((float4*)g_acc)[i] = a;
    }
}

// ---------------- projection GEMM: proj[b][k] = F[items[b]] . proj_w[k] + bias[k]
// 64x64 output tile per block, 256 threads, 4x4 microtile, K-chunks of 64.
__global__ void k_proj_gemm(const float* __restrict__ F, const float* __restrict__ W,
                            const float* __restrict__ bias, const int* __restrict__ items) {
    __shared__ float As[64][68];
    __shared__ float Ws[64][68];
    __shared__ int   ids[64];

    int b0 = blockIdx.x * 64;
    int t  = threadIdx.x;           // 0..255
    if (t < 64) ids[t] = items[b0 + t];
    __syncthreads();

    float c[4][4];
    #pragma unroll
    for (int r = 0; r < 4; r++)
        #pragma unroll
        for (int q = 0; q < 4; q++) c[r][q] = 0.f;

    int ty = t >> 4;     // 0..15
    int tx = t & 15;     // 0..15

    for (int kk = 0; kk < FEATN; kk += 64) {
        #pragma unroll
        for (int i = 0; i < 4; i++) {
            int idx = t + i * 256;       // 0..1023
            int row = idx >> 4;          // 0..63
            int q   = idx & 15;          // float4 slot
            float4 a = *(const float4*)(F + (size_t)ids[row] * FEATN + kk + q * 4);
            As[row][q * 4 + 0] = a.x; As[row][q * 4 + 1] = a.y;
            As[row][q * 4 + 2] = a.z; As[row][q * 4 + 3] = a.w;
            float4 w = *(const float4*)(W + (size_t)row * FEATN + kk + q * 4);
            Ws[row][q * 4 + 0] = w.x; Ws[row][q * 4 + 1] = w.y;
            Ws[row][q * 4 + 2] = w.z; Ws[row][q * 4 + 3] = w.w;
        }
        __syncthreads();

        #pragma unroll 16
        for (int j = 0; j < 64; j++) {
            float a[4], b[4];
            #pragma unroll
            for (int r = 0; r < 4; r++) a[r] = As[ty * 4 + r][j];
            #pragma unroll
            for (int q = 0; q < 4; q++) b[q] = Ws[tx * 4 + q][j];
            #pragma unroll
            for (int r = 0; r < 4; r++)
                #pragma unroll
                for (int q = 0; q < 4; q++) c[r][q] += a[r] * b[q];
        }
        __syncthreads();
    }

    #pragma unroll
    for (int r = 0; r < 4; r++)
        #pragma unroll
        for (int q = 0; q < 4; q++)
            g_proj[(size_t)(b0 + ty * 4 + r) * EK + tx * 4 + q] = c[r][q] + bias[tx * 4 + q];
}

// ---------------- final scoring: warp per batch element ----------------
__global__ void k_score(const float* __restrict__ Tu, const int* __restrict__ users,
                        const int* __restrict__ items, float* __restrict__ out) {
    int b = (blockIdx.x * blockDim.x + threadIdx.x) >> 5;
    if (b >= BATCHN) return;
    int lane = threadIdx.x & 31;

    int u  = users[b];
    int it = items[b];

    float2 au = *(const float2*)(g_acc + (size_t)u * EK + lane * 2);
    float2 ai = *(const float2*)(g_acc + (size_t)(NU + it) * EK + lane * 2);
    float2 p  = *(const float2*)(g_proj + (size_t)b * EK + lane * 2);
    float2 tv = *(const float2*)(Tu + (size_t)u * EK + lane * 2);

    float gdot = au.x * ai.x + au.y * ai.y;     // (acc_u . acc_i); /16 later
    float ns   = p.x * p.x + p.y * p.y;         // ||proj||^2
    float tp   = tv.x * p.x + tv.y * p.y;       // theta . proj

    #pragma unroll
    for (int o = 16; o > 0; o >>= 1) {
        gdot += __shfl_down_sync(0xffffffff, gdot, o);
        ns   += __shfl_down_sync(0xffffffff, ns,   o);
        tp   += __shfl_down_sync(0xffffffff, tp,   o);
    }
    if (lane == 0)
        out[b] = gdot * (1.0f / 16.0f) + tp / fmaxf(sqrtf(ns), 1e-12f);
}

// ---------------- launch ----------------
extern "C" void kernel_launch(void* const* d_in, const int* in_sizes, int n_in,
                              void* d_out, int out_size) {
    const float* Gu     = (const float*)d_in[0];
    const float* Gi     = (const float*)d_in[1];
    const float* Tu     = (const float*)d_in[2];
    const float* F      = (const float*)d_in[3];
    const float* proj_w = (const float*)d_in[4];
    const float* proj_b = (const float*)d_in[5];
    const int* ue       = (const int*)d_in[6];
    const int* ie       = (const int*)d_in[7];
    const int* users    = (const int*)d_in[8];
    const int* items    = (const int*)d_in[9];
    float* out          = (float*)d_out;

    const int n4blocks  = ((NKF / 4) + 255) / 256;
    const int nnblocks  = (NN + 255) / 256;
    const int neblocks  = (NE + 255) / 256;
    const int scblocks  = (NE * 32 + 255) / 256;   // warp per edge, 8 warps/block

    k_zero_deg<<<nnblocks, 256>>>();
    k_count<<<neblocks, 256>>>(ue, ie);
    k_dinv<<<nnblocks, 256>>>();
    k_init<<<n4blocks, 256>>>(Gu, Gi);

    for (int layer = 0; layer < 3; layer++) {
        int flip = layer & 1;
        k_zeroY<<<n4blocks, 256>>>(flip);
        k_scatter<<<scblocks, 256>>>(ue, ie, flip);
        k_accadd<<<n4blocks, 256>>>(flip);
    }

    k_proj_gemm<<<BATCHN / 64, 256>>>(F, proj_w, proj_b, items);
    k_score<<<(BATCHN * 32 + 255) / 256, 256>>>(Tu, users, items, out);
}

// round 7
// speedup vs baseline: 1.9467x; 1.9467x over previous
#include <cuda_runtime.h>
#include <math.h>

// Problem constants (match reference_code)
#define NU      100000
#define NI      50000
#define NN      (NU + NI)          // 150000 nodes
#define EK      64
#define FEATN   1024
#define NE      3000000            // undirected (bipartite) edges
#define NDIR    (2 * NE)           // 6,000,000 directed CSR entries
#define BATCHN  16384
#define NKF     (NN * EK)          // 9,600,000 floats per node-embedding buffer
#define NCHUNK  ((NN + 1023) / 1024)   // 147 scan chunks

// ---------------- scratch (static device globals; no runtime allocation) ---
__device__ float g_buf0[NKF];
__device__ float g_buf1[NKF];
__device__ float g_acc[NKF];
__device__ int   g_deg[NN];
__device__ float g_dinv[NN];
__device__ int   g_offs[NN + 1];
__device__ int   g_cur[NN];
__device__ int   g_bsum[NCHUNK];
__device__ int2  g_csr[NDIR];          // .x = src node, .y = bitcast(norm)
__device__ float g_proj[BATCHN * EK];

// ---------------- degree / norm ----------------
__global__ void k_zero_deg() {
    int i = blockIdx.x * blockDim.x + threadIdx.x;
    if (i < NN) g_deg[i] = 0;
}

__global__ void k_count(const int* __restrict__ ue, const int* __restrict__ ie) {
    int e = blockIdx.x * blockDim.x + threadIdx.x;
    if (e < NE) {
        atomicAdd(&g_deg[ue[e]], 1);
        atomicAdd(&g_deg[NU + ie[e]], 1);
    }
}

__global__ void k_dinv() {
    int i = blockIdx.x * blockDim.x + threadIdx.x;
    if (i < NN) {
        int d = g_deg[i];
        g_dinv[i] = (d > 0) ? rsqrtf((float)d) : 0.0f;
    }
}

// ---------------- prefix scan over degrees -> CSR offsets -----------------
__global__ void k_blocksum() {
    __shared__ int ws[32];
    int i = blockIdx.x * 1024 + threadIdx.x;
    int v = (i < NN) ? g_deg[i] : 0;
    #pragma unroll
    for (int o = 16; o > 0; o >>= 1) v += __shfl_down_sync(0xffffffff, v, o);
    if ((threadIdx.x & 31) == 0) ws[threadIdx.x >> 5] = v;
    __syncthreads();
    if (threadIdx.x < 32) {
        int t = ws[threadIdx.x];
        #pragma unroll
        for (int o = 16; o > 0; o >>= 1) t += __shfl_down_sync(0xffffffff, t, o);
        if (threadIdx.x == 0) g_bsum[blockIdx.x] = t;
    }
}

__global__ void k_scanbsum() {   // tiny serial scan, 147 elements
    if (threadIdx.x == 0) {
        int c = 0;
        for (int i = 0; i < NCHUNK; i++) { int t = g_bsum[i]; g_bsum[i] = c; c += t; }
    }
}

__global__ void k_localscan() {
    __shared__ int ws[32];
    int i = blockIdx.x * 1024 + threadIdx.x;
    int v = (i < NN) ? g_deg[i] : 0;
    int lane = threadIdx.x & 31, w = threadIdx.x >> 5;
    int s = v;
    #pragma unroll
    for (int o = 1; o < 32; o <<= 1) {
        int t = __shfl_up_sync(0xffffffff, s, o);
        if (lane >= o) s += t;
    }
    if (lane == 31) ws[w] = s;
    __syncthreads();
    if (w == 0) {
        int t = ws[lane];
        int ss = t;
        #pragma unroll
        for (int o = 1; o < 32; o <<= 1) {
            int q = __shfl_up_sync(0xffffffff, ss, o);
            if (lane >= o) ss += q;
        }
        ws[lane] = ss - t;   // exclusive
    }
    __syncthreads();
    int excl = (s - v) + ws[w] + g_bsum[blockIdx.x];
    if (i < NN) { g_offs[i] = excl; g_cur[i] = excl; }
    if (i == 0) g_offs[NN] = NDIR;
}

// ---------------- fill CSR (src id + edge norm packed) --------------------
__global__ void k_fill(const int* __restrict__ ue, const int* __restrict__ ie) {
    int e = blockIdx.x * blockDim.x + threadIdx.x;
    if (e >= NE) return;
    int u  = ue[e];
    int it = NU + ie[e];
    float nrm = g_dinv[u] * g_dinv[it];
    int nb = __float_as_int(nrm);
    int pu = atomicAdd(&g_cur[u], 1);
    g_csr[pu] = make_int2(it, nb);
    int pi = atomicAdd(&g_cur[it], 1);
    g_csr[pi] = make_int2(u, nb);
}

// ---------------- init: x0 = concat(Gu, Gi); acc = x0 ----------------
__global__ void k_init(const float* __restrict__ Gu, const float* __restrict__ Gi) {
    int i = blockIdx.x * blockDim.x + threadIdx.x;   // float4 index
    const int n4 = NKF / 4;
    if (i < n4) {
        const int gu4 = (NU * EK) / 4;
        float4 v = (i < gu4) ? ((const float4*)Gu)[i]
                             : ((const float4*)Gi)[i - gu4];
        ((float4*)g_buf0)[i] = v;
        ((float4*)g_acc)[i]  = v;
    }
}

// ---------------- pull-gather layer: one warp per destination node --------
// Each lane owns 2 of the 64 embedding columns (float2). No float atomics.
// Fuses acc += Y; skips writing Y on the last layer.
__global__ void k_gather(int flip, int last) {
    const float* __restrict__ X = flip ? g_buf1 : g_buf0;
    float* __restrict__ Y       = flip ? g_buf0 : g_buf1;
    int node = (blockIdx.x * blockDim.x + threadIdx.x) >> 5;
    if (node >= NN) return;
    int lane = threadIdx.x & 31;

    int beg = g_offs[node];
    int end = g_offs[node + 1];

    float2 s = make_float2(0.f, 0.f);
    int j = beg;
    for (; j + 4 <= end; j += 4) {
        int2 c0 = g_csr[j];
        int2 c1 = g_csr[j + 1];
        int2 c2 = g_csr[j + 2];
        int2 c3 = g_csr[j + 3];
        float2 v0 = *(const float2*)(X + (size_t)c0.x * EK + lane * 2);
        float2 v1 = *(const float2*)(X + (size_t)c1.x * EK + lane * 2);
        float2 v2 = *(const float2*)(X + (size_t)c2.x * EK + lane * 2);
        float2 v3 = *(const float2*)(X + (size_t)c3.x * EK + lane * 2);
        float n0 = __int_as_float(c0.y), n1 = __int_as_float(c1.y);
        float n2 = __int_as_float(c2.y), n3 = __int_as_float(c3.y);
        s.x += v0.x * n0 + v1.x * n1 + v2.x * n2 + v3.x * n3;
        s.y += v0.y * n0 + v1.y * n1 + v2.y * n2 + v3.y * n3;
    }
    for (; j < end; j++) {
        int2 c = g_csr[j];
        float2 v = *(const float2*)(X + (size_t)c.x * EK + lane * 2);
        float n = __int_as_float(c.y);
        s.x += v.x * n;
        s.y += v.y * n;
    }

    size_t off = (size_t)node * EK + lane * 2;
    float2 a = *(const float2*)(g_acc + off);
    a.x += s.x; a.y += s.y;
    *(float2*)(g_acc + off) = a;
    if (!last) *(float2*)(Y + off) = s;
}

// ---------------- projection GEMM: proj[b][k] = F[items[b]] . proj_w[k] + bias[k]
__global__ void k_proj_gemm(const float* __restrict__ F, const float* __restrict__ W,
                            const float* __restrict__ bias, const int* __restrict__ items) {
    __shared__ float As[64][68];
    __shared__ float Ws[64][68];
    __shared__ int   ids[64];

    int b0 = blockIdx.x * 64;
    int t  = threadIdx.x;           // 0..255
    if (t < 64) ids[t] = items[b0 + t];
    __syncthreads();

    float c[4][4];
    #pragma unroll
    for (int r = 0; r < 4; r++)
        #pragma unroll
        for (int q = 0; q < 4; q++) c[r][q] = 0.f;

    int ty = t >> 4;     // 0..15
    int tx = t & 15;     // 0..15

    for (int kk = 0; kk < FEATN; kk += 64) {
        #pragma unroll
        for (int i = 0; i < 4; i++) {
            int idx = t + i * 256;       // 0..1023
            int row = idx >> 4;          // 0..63
            int q   = idx & 15;          // float4 slot
            float4 a = *(const float4*)(F + (size_t)ids[row] * FEATN + kk + q * 4);
            As[row][q * 4 + 0] = a.x; As[row][q * 4 + 1] = a.y;
            As[row][q * 4 + 2] = a.z; As[row][q * 4 + 3] = a.w;
            float4 w = *(const float4*)(W + (size_t)row * FEATN + kk + q * 4);
            Ws[row][q * 4 + 0] = w.x; Ws[row][q * 4 + 1] = w.y;
            Ws[row][q * 4 + 2] = w.z; Ws[row][q * 4 + 3] = w.w;
        }
        __syncthreads();

        #pragma unroll 16
        for (int j = 0; j < 64; j++) {
            float a[4], b[4];
            #pragma unroll
            for (int r = 0; r < 4; r++) a[r] = As[ty * 4 + r][j];
            #pragma unroll
            for (int q = 0; q < 4; q++) b[q] = Ws[tx * 4 + q][j];
            #pragma unroll
            for (int r = 0; r < 4; r++)
                #pragma unroll
                for (int q = 0; q < 4; q++) c[r][q] += a[r] * b[q];
        }
        __syncthreads();
    }

    #pragma unroll
    for (int r = 0; r < 4; r++)
        #pragma unroll
        for (int q = 0; q < 4; q++)
            g_proj[(size_t)(b0 + ty * 4 + r) * EK + tx * 4 + q] = c[r][q] + bias[tx * 4 + q];
}

// ---------------- final scoring: warp per batch element ----------------
__global__ void k_score(const float* __restrict__ Tu, const int* __restrict__ users,
                        const int* __restrict__ items, float* __restrict__ out) {
    int b = (blockIdx.x * blockDim.x + threadIdx.x) >> 5;
    if (b >= BATCHN) return;
    int lane = threadIdx.x & 31;

    int u  = users[b];
    int it = items[b];

    float2 au = *(const float2*)(g_acc + (size_t)u * EK + lane * 2);
    float2 ai = *(const float2*)(g_acc + (size_t)(NU + it) * EK + lane * 2);
    float2 p  = *(const float2*)(g_proj + (size_t)b * EK + lane * 2);
    float2 tv = *(const float2*)(Tu + (size_t)u * EK + lane * 2);

    float gdot = au.x * ai.x + au.y * ai.y;     // (acc_u . acc_i); /16 later
    float ns   = p.x * p.x + p.y * p.y;         // ||proj||^2
    float tp   = tv.x * p.x + tv.y * p.y;       // theta . proj

    #pragma unroll
    for (int o = 16; o > 0; o >>= 1) {
        gdot += __shfl_down_sync(0xffffffff, gdot, o);
        ns   += __shfl_down_sync(0xffffffff, ns,   o);
        tp   += __shfl_down_sync(0xffffffff, tp,   o);
    }
    if (lane == 0)
        out[b] = gdot * (1.0f / 16.0f) + tp / fmaxf(sqrtf(ns), 1e-12f);
}

// ---------------- launch ----------------
extern "C" void kernel_launch(void* const* d_in, const int* in_sizes, int n_in,
                              void* d_out, int out_size) {
    const float* Gu     = (const float*)d_in[0];
    const float* Gi     = (const float*)d_in[1];
    const float* Tu     = (const float*)d_in[2];
    const float* F      = (const float*)d_in[3];
    const float* proj_w = (const float*)d_in[4];
    const float* proj_b = (const float*)d_in[5];
    const int* ue       = (const int*)d_in[6];
    const int* ie       = (const int*)d_in[7];
    const int* users    = (const int*)d_in[8];
    const int* items    = (const int*)d_in[9];
    float* out          = (float*)d_out;

    const int n4blocks = ((NKF / 4) + 255) / 256;
    const int nnblocks = (NN + 255) / 256;
    const int neblocks = (NE + 255) / 256;
    const int gwblocks = (NN * 32 + 255) / 256;    // warp per node

    // CSR build
    k_zero_deg<<<nnblocks, 256>>>();
    k_count<<<neblocks, 256>>>(ue, ie);
    k_dinv<<<nnblocks, 256>>>();
    k_blocksum<<<NCHUNK, 1024>>>();
    k_scanbsum<<<1, 32>>>();
    k_localscan<<<NCHUNK, 1024>>>();
    k_fill<<<neblocks, 256>>>(ue, ie);

    // propagation
    k_init<<<n4blocks, 256>>>(Gu, Gi);
    for (int layer = 0; layer < 3; layer++) {
        int flip = layer & 1;
        k_gather<<<gwblocks, 256>>>(flip, layer == 2);
    }

    // scoring
    k_proj_gemm<<<BATCHN / 64, 256>>>(F, proj_w, proj_b, items);
    k_score<<<(BATCHN * 32 + 255) / 256, 256>>>(Tu, users, items, out);
}

// round 9
// speedup vs baseline: 2.2596x; 1.1607x over previous
#include <cuda_runtime.h>
#include <math.h>

// Problem constants (match reference_code)
#define NU      100000
#define NI      50000
#define NN      (NU + NI)          // 150000 nodes
#define EK      64
#define FEATN   1024
#define NE      3000000            // undirected (bipartite) edges
#define NDIR    (2 * NE)           // 6,000,000 directed CSR entries
#define BATCHN  16384
#define NKF     (NN * EK)          // 9,600,000 floats per node-embedding buffer
#define NCHUNK  ((NN + 1023) / 1024)   // 147 scan chunks

// ---------------- scratch (static device globals; no runtime allocation) ---
__device__ float g_buf0[NKF];              // x0
__device__ float g_buf1[NKF];              // x1
__device__ float g_buf2[NKF];              // x2
__device__ int   g_deg[NN];
__device__ float g_dinv[NN];
__device__ int   g_offs[NN + 1];
__device__ int   g_cur[NN];
__device__ int   g_bsum[NCHUNK];
__device__ int2  g_csr[NDIR];              // .x = src node, .y = bitcast(norm)
__device__ float g_gamma[2 * BATCHN * EK]; // [0..B): user acc rows, [B..2B): item acc rows
__device__ float g_proj[BATCHN * EK];

// ---------------- degree / norm ----------------
__global__ void k_zero_deg() {
    int i = blockIdx.x * blockDim.x + threadIdx.x;
    if (i < NN) g_deg[i] = 0;
}

__global__ void k_count(const int* __restrict__ ue, const int* __restrict__ ie) {
    int e = blockIdx.x * blockDim.x + threadIdx.x;
    if (e < NE) {
        atomicAdd(&g_deg[ue[e]], 1);
        atomicAdd(&g_deg[NU + ie[e]], 1);
    }
}

__global__ void k_dinv() {
    int i = blockIdx.x * blockDim.x + threadIdx.x;
    if (i < NN) {
        int d = g_deg[i];
        g_dinv[i] = (d > 0) ? rsqrtf((float)d) : 0.0f;
    }
}

// ---------------- prefix scan over degrees -> CSR offsets -----------------
__global__ void k_blocksum() {
    __shared__ int ws[32];
    int i = blockIdx.x * 1024 + threadIdx.x;
    int v = (i < NN) ? g_deg[i] : 0;
    #pragma unroll
    for (int o = 16; o > 0; o >>= 1) v += __shfl_down_sync(0xffffffff, v, o);
    if ((threadIdx.x & 31) == 0) ws[threadIdx.x >> 5] = v;
    __syncthreads();
    if (threadIdx.x < 32) {
        int t = ws[threadIdx.x];
        #pragma unroll
        for (int o = 16; o > 0; o >>= 1) t += __shfl_down_sync(0xffffffff, t, o);
        if (threadIdx.x == 0) g_bsum[blockIdx.x] = t;
    }
}

__global__ void k_scanbsum() {   // tiny serial scan, 147 elements
    if (threadIdx.x == 0) {
        int c = 0;
        for (int i = 0; i < NCHUNK; i++) { int t = g_bsum[i]; g_bsum[i] = c; c += t; }
    }
}

__global__ void k_localscan() {
    __shared__ int ws[32];
    int i = blockIdx.x * 1024 + threadIdx.x;
    int v = (i < NN) ? g_deg[i] : 0;
    int lane = threadIdx.x & 31, w = threadIdx.x >> 5;
    int s = v;
    #pragma unroll
    for (int o = 1; o < 32; o <<= 1) {
        int t = __shfl_up_sync(0xffffffff, s, o);
        if (lane >= o) s += t;
    }
    if (lane == 31) ws[w] = s;
    __syncthreads();
    if (w == 0) {
        int t = ws[lane];
        int ss = t;
        #pragma unroll
        for (int o = 1; o < 32; o <<= 1) {
            int q = __shfl_up_sync(0xffffffff, ss, o);
            if (lane >= o) ss += q;
        }
        ws[lane] = ss - t;   // exclusive
    }
    __syncthreads();
    int excl = (s - v) + ws[w] + g_bsum[blockIdx.x];
    if (i < NN) { g_offs[i] = excl; g_cur[i] = excl; }
    if (i == 0) g_offs[NN] = NDIR;
}

// ---------------- fill CSR (src id + edge norm packed) --------------------
__global__ void k_fill(const int* __restrict__ ue, const int* __restrict__ ie) {
    int e = blockIdx.x * blockDim.x + threadIdx.x;
    if (e >= NE) return;
    int u  = ue[e];
    int it = NU + ie[e];
    float nrm = g_dinv[u] * g_dinv[it];
    int nb = __float_as_int(nrm);
    int pu = atomicAdd(&g_cur[u], 1);
    g_csr[pu] = make_int2(it, nb);
    int pi = atomicAdd(&g_cur[it], 1);
    g_csr[pi] = make_int2(u, nb);
}

// ---------------- init: x0 = concat(Gu, Gi) ----------------
__global__ void k_init(const float* __restrict__ Gu, const float* __restrict__ Gi) {
    int i = blockIdx.x * blockDim.x + threadIdx.x;   // float4 index
    const int n4 = NKF / 4;
    if (i < n4) {
        const int gu4 = (NU * EK) / 4;
        float4 v = (i < gu4) ? ((const float4*)Gu)[i]
                             : ((const float4*)Gi)[i - gu4];
        ((float4*)g_buf0)[i] = v;
    }
}

// ---------------- pull-gather layer: one warp per destination node --------
// layer 0: x0 -> x1 ; layer 1: x1 -> x2. Pure gather, no float atomics.
__global__ void k_gather(int layer) {
    const float* __restrict__ X = layer ? g_buf1 : g_buf0;
    float* __restrict__ Y       = layer ? g_buf2 : g_buf1;
    int node = (blockIdx.x * blockDim.x + threadIdx.x) >> 5;
    if (node >= NN) return;
    int lane = threadIdx.x & 31;

    int beg = g_offs[node];
    int end = g_offs[node + 1];

    float2 s = make_float2(0.f, 0.f);
    int j = beg;
    for (; j + 4 <= end; j += 4) {
        int2 c0 = g_csr[j];
        int2 c1 = g_csr[j + 1];
        int2 c2 = g_csr[j + 2];
        int2 c3 = g_csr[j + 3];
        float2 v0 = *(const float2*)(X + (size_t)c0.x * EK + lane * 2);
        float2 v1 = *(const float2*)(X + (size_t)c1.x * EK + lane * 2);
        float2 v2 = *(const float2*)(X + (size_t)c2.x * EK + lane * 2);
        float2 v3 = *(const float2*)(X + (size_t)c3.x * EK + lane * 2);
        float n0 = __int_as_float(c0.y), n1 = __int_as_float(c1.y);
        float n2 = __int_as_float(c2.y), n3 = __int_as_float(c3.y);
        s.x += v0.x * n0 + v1.x * n1 + v2.x * n2 + v3.x * n3;
        s.y += v0.y * n0 + v1.y * n1 + v2.y * n2 + v3.y * n3;
    }
    for (; j < end; j++) {
        int2 c = g_csr[j];
        float2 v = *(const float2*)(X + (size_t)c.x * EK + lane * 2);
        float n = __int_as_float(c.y);
        s.x += v.x * n;
        s.y += v.y * n;
    }

    *(float2*)(Y + (size_t)node * EK + lane * 2) = s;
}

// ---------------- layer 3 + accumulate, only at batch rows ----------------
// One warp per batch slot (32768 slots: users then items). Gathers x3 from
// x2 via CSR and writes gamma = x0 + x1 + x2 + x3 for that node.
__global__ void k_gather3(const int* __restrict__ users, const int* __restrict__ items) {
    int w = (blockIdx.x * blockDim.x + threadIdx.x) >> 5;
    if (w >= 2 * BATCHN) return;
    int lane = threadIdx.x & 31;

    int node = (w < BATCHN) ? users[w] : NU + items[w - BATCHN];

    int beg = g_offs[node];
    int end = g_offs[node + 1];

    float2 s = make_float2(0.f, 0.f);
    int j = beg;
    for (; j + 4 <= end; j += 4) {
        int2 c0 = g_csr[j];
        int2 c1 = g_csr[j + 1];
        int2 c2 = g_csr[j + 2];
        int2 c3 = g_csr[j + 3];
        float2 v0 = *(const float2*)(g_buf2 + (size_t)c0.x * EK + lane * 2);
        float2 v1 = *(const float2*)(g_buf2 + (size_t)c1.x * EK + lane * 2);
        float2 v2 = *(const float2*)(g_buf2 + (size_t)c2.x * EK + lane * 2);
        float2 v3 = *(const float2*)(g_buf2 + (size_t)c3.x * EK + lane * 2);
        float n0 = __int_as_float(c0.y), n1 = __int_as_float(c1.y);
        float n2 = __int_as_float(c2.y), n3 = __int_as_float(c3.y);
        s.x += v0.x * n0 + v1.x * n1 + v2.x * n2 + v3.x * n3;
        s.y += v0.y * n0 + v1.y * n1 + v2.y * n2 + v3.y * n3;
    }
    for (; j < end; j++) {
        int2 c = g_csr[j];
        float2 v = *(const float2*)(g_buf2 + (size_t)c.x * EK + lane * 2);
        float n = __int_as_float(c.y);
        s.x += v.x * n;
        s.y += v.y * n;
    }

    size_t off = (size_t)node * EK + lane * 2;
    float2 a0 = *(const float2*)(g_buf0 + off);
    float2 a1 = *(const float2*)(g_buf1 + off);
    float2 a2 = *(const float2*)(g_buf2 + off);
    float2 g;
    g.x = a0.x + a1.x + a2.x + s.x;
    g.y = a0.y + a1.y + a2.y + s.y;
    *(float2*)(g_gamma + (size_t)w * EK + lane * 2) = g;
}

// ---------------- projection GEMM: proj[b][k] = F[items[b]] . proj_w[k] + bias[k]
__global__ void k_proj_gemm(const float* __restrict__ F, const float* __restrict__ W,
                            const float* __restrict__ bias, const int* __restrict__ items) {
    __shared__ float As[64][68];
    __shared__ float Ws[64][68];
    __shared__ int   ids[64];

    int b0 = blockIdx.x * 64;
    int t  = threadIdx.x;           // 0..255
    if (t < 64) ids[t] = items[b0 + t];
    __syncthreads();

    float c[4][4];
    #pragma unroll
    for (int r = 0; r < 4; r++)
        #pragma unroll
        for (int q = 0; q < 4; q++) c[r][q] = 0.f;

    int ty = t >> 4;     // 0..15
    int tx = t & 15;     // 0..15

    for (int kk = 0; kk < FEATN; kk += 64) {
        #pragma unroll
        for (int i = 0; i < 4; i++) {
            int idx = t + i * 256;       // 0..1023
            int row = idx >> 4;          // 0..63
            int q   = idx & 15;          // float4 slot
            float4 a = *(const float4*)(F + (size_t)ids[row] * FEATN + kk + q * 4);
            As[row][q * 4 + 0] = a.x; As[row][q * 4 + 1] = a.y;
            As[row][q * 4 + 2] = a.z; As[row][q * 4 + 3] = a.w;
            float4 w = *(const float4*)(W + (size_t)row * FEATN + kk + q * 4);
            Ws[row][q * 4 + 0] = w.x; Ws[row][q * 4 + 1] = w.y;
            Ws[row][q * 4 + 2] = w.z; Ws[row][q * 4 + 3] = w.w;
        }
        __syncthreads();

        #pragma unroll 16
        for (int j = 0; j < 64; j++) {
            float a[4], b[4];
            #pragma unroll
            for (int r = 0; r < 4; r++) a[r] = As[ty * 4 + r][j];
            #pragma unroll
            for (int q = 0; q < 4; q++) b[q] = Ws[tx * 4 + q][j];
            #pragma unroll
            for (int r = 0; r < 4; r++)
                #pragma unroll
                for (int q = 0; q < 4; q++) c[r][q] += a[r] * b[q];
        }
        __syncthreads();
    }

    #pragma unroll
    for (int r = 0; r < 4; r++)
        #pragma unroll
        for (int q = 0; q < 4; q++)
            g_proj[(size_t)(b0 + ty * 4 + r) * EK + tx * 4 + q] = c[r][q] + bias[tx * 4 + q];
}

// ---------------- final scoring: warp per batch element ----------------
__global__ void k_score(const float* __restrict__ Tu, const int* __restrict__ users,
                        float* __restrict__ out) {
    int b = (blockIdx.x * blockDim.x + threadIdx.x) >> 5;
    if (b >= BATCHN) return;
    int lane = threadIdx.x & 31;

    int u = users[b];

    float2 au = *(const float2*)(g_gamma + (size_t)b * EK + lane * 2);
    float2 ai = *(const float2*)(g_gamma + (size_t)(BATCHN + b) * EK + lane * 2);
    float2 p  = *(const float2*)(g_proj + (size_t)b * EK + lane * 2);
    float2 tv = *(const float2*)(Tu + (size_t)u * EK + lane * 2);

    float gdot = au.x * ai.x + au.y * ai.y;     // (acc_u . acc_i); /16 later
    float ns   = p.x * p.x + p.y * p.y;         // ||proj||^2
    float tp   = tv.x * p.x + tv.y * p.y;       // theta . proj

    #pragma unroll
    for (int o = 16; o > 0; o >>= 1) {
        gdot += __shfl_down_sync(0xffffffff, gdot, o);
        ns   += __shfl_down_sync(0xffffffff, ns,   o);
        tp   += __shfl_down_sync(0xffffffff, tp,   o);
    }
    if (lane == 0)
        out[b] = gdot * (1.0f / 16.0f) + tp / fmaxf(sqrtf(ns), 1e-12f);
}

// ---------------- launch ----------------
extern "C" void kernel_launch(void* const* d_in, const int* in_sizes, int n_in,
                              void* d_out, int out_size) {
    const float* Gu     = (const float*)d_in[0];
    const float* Gi     = (const float*)d_in[1];
    const float* Tu     = (const float*)d_in[2];
    const float* F      = (const float*)d_in[3];
    const float* proj_w = (const float*)d_in[4];
    const float* proj_b = (const float*)d_in[5];
    const int* ue       = (const int*)d_in[6];
    const int* ie       = (const int*)d_in[7];
    const int* users    = (const int*)d_in[8];
    const int* items    = (const int*)d_in[9];
    float* out          = (float*)d_out;

    const int n4blocks = ((NKF / 4) + 255) / 256;
    const int nnblocks = (NN + 255) / 256;
    const int neblocks = (NE + 255) / 256;
    const int gwblocks = (NN * 32 + 255) / 256;          // warp per node
    const int g3blocks = (2 * BATCHN * 32 + 255) / 256;  // warp per batch slot

    // CSR build
    k_zero_deg<<<nnblocks, 256>>>();
    k_count<<<neblocks, 256>>>(ue, ie);
    k_dinv<<<nnblocks, 256>>>();
    k_blocksum<<<NCHUNK, 1024>>>();
    k_scanbsum<<<1, 32>>>();
    k_localscan<<<NCHUNK, 1024>>>();
    k_fill<<<neblocks, 256>>>(ue, ie);

    // propagation: x0 -> x1 -> x2, then batch-only layer 3 + accumulate
    k_init<<<n4blocks, 256>>>(Gu, Gi);
    k_gather<<<gwblocks, 256>>>(0);
    k_gather<<<gwblocks, 256>>>(1);
    k_gather3<<<g3blocks, 256>>>(users, items);

    // scoring
    k_proj_gemm<<<BATCHN / 64, 256>>>(F, proj_w, proj_b, items);
    k_score<<<(BATCHN * 32 + 255) / 256, 256>>>(Tu, users, out);
}